// round 2
// baseline (speedup 1.0000x reference)
#include <cuda_runtime.h>
#include <cstdint>
#include <math_constants.h>

#define DCOLS 2048
#define THREADS 256
#define CAP 1024

__device__ __forceinline__ float michelot_list(const float* c, int k) {
    // Exact sparsemax threshold over candidate list c[0..k) (all > max-1 bracket).
    float S = 0.f;
    for (int i = 0; i < k; i++) S += c[i];
    float tau = (S - 1.0f) / (float)k;
    int prevc = k;
    for (int it = 0; it < CAP + 2; it++) {
        float s = 0.f; int cc = 0;
        for (int i = 0; i < k; i++) {
            float z = c[i];
            if (z > tau) { s += z; cc++; }
        }
        if (cc == prevc || cc == 0) break;
        tau = (s - 1.0f) / (float)cc;
        prevc = cc;
    }
    return tau;
}

__device__ float michelot_row_global(const float* xr, const int* mr) {
    // Fallback (statistically unreachable for this data): serial Michelot over full row.
    float S = 0.f; int k = 0;
    for (int i = 0; i < DCOLS; i++) {
        if (mr[i]) { S += xr[i]; k++; }
    }
    float tau = (S - 1.0f) / (float)k;
    int prevc = k;
    for (int it = 0; it < DCOLS + 2; it++) {
        float s = 0.f; int cc = 0;
        for (int i = 0; i < DCOLS; i++) {
            if (mr[i]) {
                float z = xr[i];
                if (z > tau) { s += z; cc++; }
            }
        }
        if (cc == prevc || cc == 0) break;
        tau = (s - 1.0f) / (float)cc;
        prevc = cc;
    }
    return tau;
}

__global__ __launch_bounds__(THREADS) void sparsemax_kernel(
    const float* __restrict__ x,
    const int* __restrict__ mask,
    float* __restrict__ out)
{
    const int row = blockIdx.x;
    const int t = threadIdx.x;

    const float* xrow = x + (size_t)row * DCOLS;
    const int* mrow = mask + (size_t)row * DCOLS;
    float* orow_f = out + (size_t)row * DCOLS;

    const float4* xr = reinterpret_cast<const float4*>(xrow);
    const int4* mr = reinterpret_cast<const int4*>(mrow);
    float4* orow = reinterpret_cast<float4*>(orow_f);

    __shared__ float s_red[8];
    __shared__ int   s_redi[8];
    __shared__ int   s_cnt;
    __shared__ float s_tau;
    __shared__ float s_cand[CAP];

    // Load 8 values + 8 mask words per thread (coalesced 128-bit accesses)
    float4 v0 = xr[t];
    float4 v1 = xr[t + THREADS];
    int4 m0 = mr[t];
    int4 m1 = mr[t + THREADS];

    float vals[8] = {v0.x, v0.y, v0.z, v0.w, v1.x, v1.y, v1.z, v1.w};
    bool  act[8]  = {m0.x != 0, m0.y != 0, m0.z != 0, m0.w != 0,
                     m1.x != 0, m1.y != 0, m1.z != 0, m1.w != 0};

    // ---- Phase 1: block reduce -> active max, active count ----
    float mx = -CUDART_INF_F;
    int cnt = 0;
    #pragma unroll
    for (int i = 0; i < 8; i++) {
        if (act[i]) { mx = fmaxf(mx, vals[i]); cnt++; }
    }
    #pragma unroll
    for (int o = 16; o; o >>= 1) {
        mx = fmaxf(mx, __shfl_xor_sync(0xFFFFFFFFu, mx, o));
        cnt += __shfl_xor_sync(0xFFFFFFFFu, cnt, o);
    }
    int warp = t >> 5, lane = t & 31;
    if (lane == 0) { s_red[warp] = mx; s_redi[warp] = cnt; }
    if (t == 0) s_cnt = 0;
    __syncthreads();
    if (t == 0) {
        float m = -CUDART_INF_F; int c = 0;
        #pragma unroll
        for (int i = 0; i < 8; i++) { m = fmaxf(m, s_red[i]); c += s_redi[i]; }
        s_red[0] = m; s_redi[0] = c;
    }
    __syncthreads();
    const float allmax = s_red[0];
    const int allcnt = s_redi[0];

    if (allcnt == 0) {
        // no active entries: all-zeros row
        float4 z4 = make_float4(0.f, 0.f, 0.f, 0.f);
        orow[t] = z4;
        orow[t + THREADS] = z4;
        return;
    }

    // ---- Phase 2: compact candidates {active & x > max-1} into shared ----
    const float thresh = allmax - 1.0f;
    #pragma unroll
    for (int i = 0; i < 8; i++) {
        if (act[i] && vals[i] > thresh) {
            int idx = atomicAdd(&s_cnt, 1);
            if (idx < CAP) s_cand[idx] = vals[i];
        }
    }
    __syncthreads();
    const int k = s_cnt;

    // ---- Phase 3: exact threshold (serial, tiny candidate set) ----
    if (t == 0) {
        float tau;
        if (k <= CAP) tau = michelot_list(s_cand, k);
        else          tau = michelot_row_global(xrow, mrow);
        s_tau = tau;
    }
    __syncthreads();
    const float tau = s_tau;

    // ---- Phase 4: write p = relu(x - tau) on active positions, else 0 ----
    float4 o0, o1;
    o0.x = act[0] ? fmaxf(vals[0] - tau, 0.f) : 0.f;
    o0.y = act[1] ? fmaxf(vals[1] - tau, 0.f) : 0.f;
    o0.z = act[2] ? fmaxf(vals[2] - tau, 0.f) : 0.f;
    o0.w = act[3] ? fmaxf(vals[3] - tau, 0.f) : 0.f;
    o1.x = act[4] ? fmaxf(vals[4] - tau, 0.f) : 0.f;
    o1.y = act[5] ? fmaxf(vals[5] - tau, 0.f) : 0.f;
    o1.z = act[6] ? fmaxf(vals[6] - tau, 0.f) : 0.f;
    o1.w = act[7] ? fmaxf(vals[7] - tau, 0.f) : 0.f;
    orow[t] = o0;
    orow[t + THREADS] = o1;
}

extern "C" void kernel_launch(void* const* d_in, const int* in_sizes, int n_in,
                              void* d_out, int out_size) {
    const float* x = (const float*)d_in[0];
    const int* mask = (const int*)d_in[1];
    float* out = (float*)d_out;

    const int rows = out_size / DCOLS;   // 16384
    sparsemax_kernel<<<rows, THREADS>>>(x, mask, out);
}